// round 1
// baseline (speedup 1.0000x reference)
#include <cuda_runtime.h>
#include <math.h>

// Problem constants
#define NU 50000
#define NI 50000
#define NN 100000          // NU + NI
#define DD 64
#define NNZ 3200000
#define NLAYERS 3
#define NB 4096
#define L2_REG 1e-5f

// scan config
#define SCAN_CHUNK 1024
#define SCAN_NBLK ((NN + SCAN_CHUNK - 1) / SCAN_CHUNK)   // 98

// ---------------- device scratch (no allocs allowed) ----------------
__device__ float g_E0[NN * DD];
__device__ float g_E1[NN * DD];
__device__ float g_Lmul[NN * DD];
__device__ float g_alle[NN * DD * (NLAYERS + 1)];   // [N, 256]
__device__ int   g_deg[NN];
__device__ int   g_rowptr[NN + 1];
__device__ int   g_cursor[NN];
__device__ int   g_colp[NNZ];
__device__ float g_valp[NNZ];
__device__ int   g_bsum[SCAN_NBLK];
__device__ int   g_boff[SCAN_NBLK];
__device__ float g_acc[4];   // bpr_sum, sum u^2, sum p^2, sum n^2

// ---------------- small setup kernels ----------------
__global__ void k_zero(void) {
    int i = blockIdx.x * blockDim.x + threadIdx.x;
    if (i < NN) g_deg[i] = 0;
    if (i < 4) g_acc[i] = 0.0f;
}

__global__ void k_count(const int* __restrict__ rows) {
    int e = blockIdx.x * blockDim.x + threadIdx.x;
    if (e < NNZ) atomicAdd(&g_deg[rows[e]], 1);
}

// inclusive scan per 1024-chunk
__global__ void k_scan1(void) {
    __shared__ int s[SCAN_CHUNK];
    int t = threadIdx.x;
    int i = blockIdx.x * SCAN_CHUNK + t;
    int v = (i < NN) ? g_deg[i] : 0;
    s[t] = v;
    __syncthreads();
    for (int off = 1; off < SCAN_CHUNK; off <<= 1) {
        int x = 0;
        if (t >= off) x = s[t - off];
        __syncthreads();
        s[t] += x;
        __syncthreads();
    }
    if (i < NN) g_rowptr[1 + i] = s[t];
    if (t == SCAN_CHUNK - 1) g_bsum[blockIdx.x] = s[t];
}

__global__ void k_scan2(void) {
    // single thread: 98 elements
    if (threadIdx.x == 0 && blockIdx.x == 0) {
        int run = 0;
        for (int b = 0; b < SCAN_NBLK; b++) {
            run += g_bsum[b];
            g_boff[b] = run;
        }
        g_rowptr[0] = 0;
    }
}

__global__ void k_scan3(void) {
    int i = blockIdx.x * blockDim.x + threadIdx.x;
    if (i < NN) {
        int b = i / SCAN_CHUNK;
        if (b > 0) g_rowptr[1 + i] += g_boff[b - 1];
        g_cursor[i] = g_rowptr[i];
    }
}

__global__ void k_scatter(const int* __restrict__ rows,
                          const int* __restrict__ cols,
                          const float* __restrict__ vals) {
    int e = blockIdx.x * blockDim.x + threadIdx.x;
    if (e < NNZ) {
        int r = rows[e];
        int p = atomicAdd(&g_cursor[r], 1);
        g_colp[p] = cols[e];
        g_valp[p] = vals[e];
    }
}

// build E = concat(user_embed, item_embed); also write all_e block 0
__global__ void k_init_E(const float* __restrict__ ue, const float* __restrict__ ie) {
    // float4 granularity: N*16 float4s
    int i = blockIdx.x * blockDim.x + threadIdx.x;
    if (i >= NN * (DD / 4)) return;
    int n = i >> 4;          // node
    int c = i & 15;          // float4 col within row
    const float4* src;
    int srow;
    if (n < NU) { src = (const float4*)ue; srow = n; }
    else        { src = (const float4*)ie; srow = n - NU; }
    float4 v = src[srow * 16 + c];
    ((float4*)g_E0)[i] = v;
    // all_e row has 64 float4; block 0 at cols [0,16)
    ((float4*)g_alle)[n * 64 + c] = v;
}

// ---------------- SpMM: warp per node, CSR, no atomics ----------------
__global__ void k_spmm(int cur) {
    const float* E = cur ? g_E1 : g_E0;
    int warp = (blockIdx.x * blockDim.x + threadIdx.x) >> 5;
    int lane = threadIdx.x & 31;
    if (warp >= NN) return;
    int start = g_rowptr[warp];
    int end   = g_rowptr[warp + 1];
    const float2* E2 = (const float2*)E;
    float2 acc = make_float2(0.0f, 0.0f);
    int e0 = start;
    for (; e0 + 32 <= end; e0 += 32) {
        int   c = g_colp[e0 + lane];
        float v = g_valp[e0 + lane];
        #pragma unroll
        for (int j = 0; j < 32; j++) {
            int   cj = __shfl_sync(0xffffffffu, c, j);
            float vj = __shfl_sync(0xffffffffu, v, j);
            float2 ev = E2[cj * 32 + lane];
            acc.x = fmaf(vj, ev.x, acc.x);
            acc.y = fmaf(vj, ev.y, acc.y);
        }
    }
    int rem = end - e0;
    if (rem > 0) {
        int c = 0; float v = 0.0f;
        if (lane < rem) { c = g_colp[e0 + lane]; v = g_valp[e0 + lane]; }
        for (int j = 0; j < rem; j++) {
            int   cj = __shfl_sync(0xffffffffu, c, j);
            float vj = __shfl_sync(0xffffffffu, v, j);
            float2 ev = E2[cj * 32 + lane];
            acc.x = fmaf(vj, ev.x, acc.x);
            acc.y = fmaf(vj, ev.y, acc.y);
        }
    }
    ((float2*)g_Lmul)[warp * 32 + lane] = acc;
}

// ---------------- fused GEMM + leaky_relu + norm + dual store ----------------
// block: 128 rows, 256 threads (tx 0..15 -> 4 cols, ty 0..15 -> 8 rows stride 16)
#define AS_STRIDE 66
#define GEMM_SMEM_FLOATS (2 * 128 * AS_STRIDE + 2 * 64 * 64 + 128)

__global__ void __launch_bounds__(256, 2) k_gemm(int cur, int l,
                                                 const float* __restrict__ W1,
                                                 const float* __restrict__ b1,
                                                 const float* __restrict__ W2,
                                                 const float* __restrict__ b2) {
    extern __shared__ float smem[];
    float* As    = smem;                         // [128][66]
    float* Rs    = As + 128 * AS_STRIDE;         // [128][66]
    float* W1s   = Rs + 128 * AS_STRIDE;         // [64][64]
    float* W2s   = W1s + 64 * 64;                // [64][64]
    float* rnorm = W2s + 64 * 64;                // [128]

    const float* Ecur  = cur ? g_E1 : g_E0;
    float*       Enext = cur ? g_E0 : g_E1;

    int tid = threadIdx.x;
    int tx = tid & 15;        // col group
    int ty = tid >> 4;        // row base
    int j0 = tx * 4;
    int n0 = blockIdx.x * 128;
    int lw = l * 64 * 64;
    int lb = l * 64;

    // load weights
    for (int i = tid; i < 4096; i += 256) {
        W1s[i] = W1[lw + i];
        W2s[i] = W2[lw + i];
    }
    if (tid < 128) rnorm[tid] = 0.0f;

    // stage a = Lmul + E, r = Lmul * E
    for (int idx = tid; idx < 128 * 16; idx += 256) {
        int row = idx >> 4;
        int k4  = (idx & 15) << 2;
        int n = n0 + row;
        float4 lm, ev;
        if (n < NN) {
            lm = *(const float4*)&g_Lmul[n * DD + k4];
            ev = *(const float4*)&Ecur[n * DD + k4];
        } else {
            lm = make_float4(0, 0, 0, 0);
            ev = make_float4(0, 0, 0, 0);
        }
        float* a = &As[row * AS_STRIDE + k4];
        float* r = &Rs[row * AS_STRIDE + k4];
        a[0] = lm.x + ev.x; a[1] = lm.y + ev.y; a[2] = lm.z + ev.z; a[3] = lm.w + ev.w;
        r[0] = lm.x * ev.x; r[1] = lm.y * ev.y; r[2] = lm.z * ev.z; r[3] = lm.w * ev.w;
    }
    __syncthreads();

    float acc[8][4];
    {
        float bx = b1[lb + j0 + 0] + b2[lb + j0 + 0];
        float by = b1[lb + j0 + 1] + b2[lb + j0 + 1];
        float bz = b1[lb + j0 + 2] + b2[lb + j0 + 2];
        float bw = b1[lb + j0 + 3] + b2[lb + j0 + 3];
        #pragma unroll
        for (int m = 0; m < 8; m++) {
            acc[m][0] = bx; acc[m][1] = by; acc[m][2] = bz; acc[m][3] = bw;
        }
    }

    #pragma unroll 8
    for (int k = 0; k < 64; k++) {
        float4 w1 = *(const float4*)&W1s[k * 64 + j0];
        float4 w2 = *(const float4*)&W2s[k * 64 + j0];
        #pragma unroll
        for (int m = 0; m < 8; m++) {
            float a = As[(ty + 16 * m) * AS_STRIDE + k];
            float r = Rs[(ty + 16 * m) * AS_STRIDE + k];
            acc[m][0] = fmaf(a, w1.x, fmaf(r, w2.x, acc[m][0]));
            acc[m][1] = fmaf(a, w1.y, fmaf(r, w2.y, acc[m][1]));
            acc[m][2] = fmaf(a, w1.z, fmaf(r, w2.z, acc[m][2]));
            acc[m][3] = fmaf(a, w1.w, fmaf(r, w2.w, acc[m][3]));
        }
    }

    // leaky relu + partial row norms
    #pragma unroll
    for (int m = 0; m < 8; m++) {
        float local = 0.0f;
        #pragma unroll
        for (int c = 0; c < 4; c++) {
            float v = acc[m][c];
            v = (v >= 0.0f) ? v : 0.2f * v;
            acc[m][c] = v;
            local = fmaf(v, v, local);
        }
        atomicAdd(&rnorm[ty + 16 * m], local);
    }
    __syncthreads();

    int colblk = (l + 1) * 64;
    #pragma unroll
    for (int m = 0; m < 8; m++) {
        int row = ty + 16 * m;
        int n = n0 + row;
        if (n < NN) {
            float nrm = sqrtf(rnorm[row]);
            float inv = 1.0f / fmaxf(nrm, 1e-12f);
            float4 v = make_float4(acc[m][0], acc[m][1], acc[m][2], acc[m][3]);
            *(float4*)&Enext[n * DD + j0] = v;
            float4 vn = make_float4(v.x * inv, v.y * inv, v.z * inv, v.w * inv);
            *(float4*)&g_alle[n * 256 + colblk + j0] = vn;
        }
    }
}

// ---------------- final loss ----------------
__global__ void k_loss(const int* __restrict__ users,
                       const int* __restrict__ pos,
                       const int* __restrict__ neg) {
    int warp = (blockIdx.x * blockDim.x + threadIdx.x) >> 5;
    int lane = threadIdx.x & 31;
    if (warp >= NB) return;
    int uu = users[warp];
    int pp = pos[warp];
    int nn = neg[warp];
    const float4* A4 = (const float4*)g_alle;   // row = 64 float4
    float pd = 0, nd = 0, su = 0, sp = 0, sn = 0;
    #pragma unroll
    for (int t = 0; t < 2; t++) {
        float4 u = A4[uu * 64 + lane * 2 + t];
        float4 p = A4[pp * 64 + lane * 2 + t];
        float4 q = A4[nn * 64 + lane * 2 + t];
        pd += u.x * p.x + u.y * p.y + u.z * p.z + u.w * p.w;
        nd += u.x * q.x + u.y * q.y + u.z * q.z + u.w * q.w;
        su += u.x * u.x + u.y * u.y + u.z * u.z + u.w * u.w;
        sp += p.x * p.x + p.y * p.y + p.z * p.z + p.w * p.w;
        sn += q.x * q.x + q.y * q.y + q.z * q.z + q.w * q.w;
    }
    #pragma unroll
    for (int off = 16; off > 0; off >>= 1) {
        pd += __shfl_xor_sync(0xffffffffu, pd, off);
        nd += __shfl_xor_sync(0xffffffffu, nd, off);
        su += __shfl_xor_sync(0xffffffffu, su, off);
        sp += __shfl_xor_sync(0xffffffffu, sp, off);
        sn += __shfl_xor_sync(0xffffffffu, sn, off);
    }
    if (lane == 0) {
        float d = pd - nd;
        // stable log_sigmoid
        float ls = fminf(d, 0.0f) - log1pf(expf(-fabsf(d)));
        atomicAdd(&g_acc[0], ls);
        atomicAdd(&g_acc[1], su);
        atomicAdd(&g_acc[2], sp);
        atomicAdd(&g_acc[3], sn);
    }
}

__global__ void k_finalize(float* out) {
    float bpr = -g_acc[0] / (float)NB;
    float l2norm = (g_acc[1] + g_acc[2] + sqrtf(g_acc[3])) * 0.5f;
    out[0] = bpr + L2_REG * l2norm / (float)NB;
}

// ---------------- launch ----------------
extern "C" void kernel_launch(void* const* d_in, const int* in_sizes, int n_in,
                              void* d_out, int out_size) {
    const int*   users = (const int*)d_in[0];
    const int*   pos   = (const int*)d_in[1];
    const int*   neg   = (const int*)d_in[2];
    const int*   rows  = (const int*)d_in[3];
    const int*   cols  = (const int*)d_in[4];
    const float* vals  = (const float*)d_in[5];
    const float* ue    = (const float*)d_in[6];
    const float* ie    = (const float*)d_in[7];
    const float* W1    = (const float*)d_in[8];
    const float* b1    = (const float*)d_in[9];
    const float* W2    = (const float*)d_in[10];
    const float* b2    = (const float*)d_in[11];
    float* out = (float*)d_out;

    static int smem_set = 0;
    (void)smem_set;
    cudaFuncSetAttribute(k_gemm, cudaFuncAttributeMaxDynamicSharedMemorySize,
                         GEMM_SMEM_FLOATS * sizeof(float));

    // CSR build
    k_zero<<<(NN + 255) / 256, 256>>>();
    k_count<<<(NNZ + 255) / 256, 256>>>(rows);
    k_scan1<<<SCAN_NBLK, SCAN_CHUNK>>>();
    k_scan2<<<1, 32>>>();
    k_scan3<<<(NN + 255) / 256, 256>>>();
    k_scatter<<<(NNZ + 255) / 256, 256>>>(rows, cols, vals);

    // E init
    k_init_E<<<(NN * 16 + 255) / 256, 256>>>(ue, ie);

    // layers
    int cur = 0;
    for (int l = 0; l < NLAYERS; l++) {
        k_spmm<<<(NN + 7) / 8, 256>>>(cur);
        k_gemm<<<(NN + 127) / 128, 256, GEMM_SMEM_FLOATS * sizeof(float)>>>(
            cur, l, W1, b1, W2, b2);
        cur ^= 1;
    }

    // loss
    k_loss<<<(NB * 32 + 255) / 256, 256>>>(users, pos, neg);
    k_finalize<<<1, 1>>>(out);
}

// round 2
// speedup vs baseline: 1.0003x; 1.0003x over previous
#include <cuda_runtime.h>
#include <math.h>

// Problem constants
#define NU 50000
#define NI 50000
#define NN 100000          // NU + NI
#define DD 64
#define NNZ 3200000
#define NLAYERS 3
#define NB 4096
#define L2_REG 1e-5f

// scan config
#define SCAN_CHUNK 1024
#define SCAN_NBLK ((NN + SCAN_CHUNK - 1) / SCAN_CHUNK)   // 98

// ---------------- device scratch (no allocs allowed) ----------------
__device__ float g_E0[NN * DD];
__device__ float g_E1[NN * DD];
__device__ float g_Lmul[NN * DD];
__device__ float g_alle[NN * DD * (NLAYERS + 1)];   // [N, 256]
__device__ int   g_deg[NN];
__device__ int   g_rowptr[NN + 1];
__device__ int   g_cursor[NN];
__device__ int   g_colp[NNZ];
__device__ float g_valp[NNZ];
__device__ int   g_bsum[SCAN_NBLK];
__device__ int   g_boff[SCAN_NBLK];
__device__ float g_acc[4];   // bpr_sum, sum u^2, sum p^2, sum n^2

// ---------------- small setup kernels ----------------
__global__ void k_zero(void) {
    int i = blockIdx.x * blockDim.x + threadIdx.x;
    if (i < NN) g_deg[i] = 0;
    if (i < 4) g_acc[i] = 0.0f;
}

__global__ void k_count(const int* __restrict__ rows) {
    int e = blockIdx.x * blockDim.x + threadIdx.x;
    if (e < NNZ) atomicAdd(&g_deg[rows[e]], 1);
}

// inclusive scan per 1024-chunk
__global__ void k_scan1(void) {
    __shared__ int s[SCAN_CHUNK];
    int t = threadIdx.x;
    int i = blockIdx.x * SCAN_CHUNK + t;
    int v = (i < NN) ? g_deg[i] : 0;
    s[t] = v;
    __syncthreads();
    for (int off = 1; off < SCAN_CHUNK; off <<= 1) {
        int x = 0;
        if (t >= off) x = s[t - off];
        __syncthreads();
        s[t] += x;
        __syncthreads();
    }
    if (i < NN) g_rowptr[1 + i] = s[t];
    if (t == SCAN_CHUNK - 1) g_bsum[blockIdx.x] = s[t];
}

__global__ void k_scan2(void) {
    // single thread: 98 elements
    if (threadIdx.x == 0 && blockIdx.x == 0) {
        int run = 0;
        for (int b = 0; b < SCAN_NBLK; b++) {
            run += g_bsum[b];
            g_boff[b] = run;
        }
        g_rowptr[0] = 0;
    }
}

__global__ void k_scan3(void) {
    int i = blockIdx.x * blockDim.x + threadIdx.x;
    if (i < NN) {
        int b = i / SCAN_CHUNK;
        if (b > 0) g_rowptr[1 + i] += g_boff[b - 1];
        g_cursor[i] = g_rowptr[i];
    }
}

__global__ void k_scatter(const int* __restrict__ rows,
                          const int* __restrict__ cols,
                          const float* __restrict__ vals) {
    int e = blockIdx.x * blockDim.x + threadIdx.x;
    if (e < NNZ) {
        int r = rows[e];
        int p = atomicAdd(&g_cursor[r], 1);
        g_colp[p] = cols[e];
        g_valp[p] = vals[e];
    }
}

// build E = concat(user_embed, item_embed); also write all_e block 0
__global__ void k_init_E(const float* __restrict__ ue, const float* __restrict__ ie) {
    // float4 granularity: N*16 float4s
    int i = blockIdx.x * blockDim.x + threadIdx.x;
    if (i >= NN * (DD / 4)) return;
    int n = i >> 4;          // node
    int c = i & 15;          // float4 col within row
    const float4* src;
    int srow;
    if (n < NU) { src = (const float4*)ue; srow = n; }
    else        { src = (const float4*)ie; srow = n - NU; }
    float4 v = src[srow * 16 + c];
    ((float4*)g_E0)[i] = v;
    // all_e row has 64 float4; block 0 at cols [0,16)
    ((float4*)g_alle)[n * 64 + c] = v;
}

// ---------------- SpMM: warp per node, CSR, no atomics ----------------
__global__ void k_spmm(int cur) {
    const float* E = cur ? g_E1 : g_E0;
    int warp = (blockIdx.x * blockDim.x + threadIdx.x) >> 5;
    int lane = threadIdx.x & 31;
    if (warp >= NN) return;
    int start = g_rowptr[warp];
    int end   = g_rowptr[warp + 1];
    const float2* E2 = (const float2*)E;
    float2 acc = make_float2(0.0f, 0.0f);
    int e0 = start;
    for (; e0 + 32 <= end; e0 += 32) {
        int   c = g_colp[e0 + lane];
        float v = g_valp[e0 + lane];
        #pragma unroll
        for (int j = 0; j < 32; j++) {
            int   cj = __shfl_sync(0xffffffffu, c, j);
            float vj = __shfl_sync(0xffffffffu, v, j);
            float2 ev = E2[cj * 32 + lane];
            acc.x = fmaf(vj, ev.x, acc.x);
            acc.y = fmaf(vj, ev.y, acc.y);
        }
    }
    int rem = end - e0;
    if (rem > 0) {
        int c = 0; float v = 0.0f;
        if (lane < rem) { c = g_colp[e0 + lane]; v = g_valp[e0 + lane]; }
        for (int j = 0; j < rem; j++) {
            int   cj = __shfl_sync(0xffffffffu, c, j);
            float vj = __shfl_sync(0xffffffffu, v, j);
            float2 ev = E2[cj * 32 + lane];
            acc.x = fmaf(vj, ev.x, acc.x);
            acc.y = fmaf(vj, ev.y, acc.y);
        }
    }
    ((float2*)g_Lmul)[warp * 32 + lane] = acc;
}

// ---------------- fused GEMM + leaky_relu + norm + dual store ----------------
// block: 128 rows, 256 threads (tx 0..15 -> 4 cols, ty 0..15 -> 8 rows stride 16)
#define AS_STRIDE 66
#define GEMM_SMEM_FLOATS (2 * 128 * AS_STRIDE + 2 * 64 * 64 + 128)

__global__ void __launch_bounds__(256, 2) k_gemm(int cur, int l,
                                                 const float* __restrict__ W1,
                                                 const float* __restrict__ b1,
                                                 const float* __restrict__ W2,
                                                 const float* __restrict__ b2) {
    extern __shared__ float smem[];
    float* As    = smem;                         // [128][66]
    float* Rs    = As + 128 * AS_STRIDE;         // [128][66]
    float* W1s   = Rs + 128 * AS_STRIDE;         // [64][64]
    float* W2s   = W1s + 64 * 64;                // [64][64]
    float* rnorm = W2s + 64 * 64;                // [128]

    const float* Ecur  = cur ? g_E1 : g_E0;
    float*       Enext = cur ? g_E0 : g_E1;

    int tid = threadIdx.x;
    int tx = tid & 15;        // col group
    int ty = tid >> 4;        // row base
    int j0 = tx * 4;
    int n0 = blockIdx.x * 128;
    int lw = l * 64 * 64;
    int lb = l * 64;

    // load weights
    for (int i = tid; i < 4096; i += 256) {
        W1s[i] = W1[lw + i];
        W2s[i] = W2[lw + i];
    }
    if (tid < 128) rnorm[tid] = 0.0f;

    // stage a = Lmul + E, r = Lmul * E
    for (int idx = tid; idx < 128 * 16; idx += 256) {
        int row = idx >> 4;
        int k4  = (idx & 15) << 2;
        int n = n0 + row;
        float4 lm, ev;
        if (n < NN) {
            lm = *(const float4*)&g_Lmul[n * DD + k4];
            ev = *(const float4*)&Ecur[n * DD + k4];
        } else {
            lm = make_float4(0, 0, 0, 0);
            ev = make_float4(0, 0, 0, 0);
        }
        float* a = &As[row * AS_STRIDE + k4];
        float* r = &Rs[row * AS_STRIDE + k4];
        a[0] = lm.x + ev.x; a[1] = lm.y + ev.y; a[2] = lm.z + ev.z; a[3] = lm.w + ev.w;
        r[0] = lm.x * ev.x; r[1] = lm.y * ev.y; r[2] = lm.z * ev.z; r[3] = lm.w * ev.w;
    }
    __syncthreads();

    float acc[8][4];
    {
        float bx = b1[lb + j0 + 0] + b2[lb + j0 + 0];
        float by = b1[lb + j0 + 1] + b2[lb + j0 + 1];
        float bz = b1[lb + j0 + 2] + b2[lb + j0 + 2];
        float bw = b1[lb + j0 + 3] + b2[lb + j0 + 3];
        #pragma unroll
        for (int m = 0; m < 8; m++) {
            acc[m][0] = bx; acc[m][1] = by; acc[m][2] = bz; acc[m][3] = bw;
        }
    }

    #pragma unroll 8
    for (int k = 0; k < 64; k++) {
        float4 w1 = *(const float4*)&W1s[k * 64 + j0];
        float4 w2 = *(const float4*)&W2s[k * 64 + j0];
        #pragma unroll
        for (int m = 0; m < 8; m++) {
            float a = As[(ty + 16 * m) * AS_STRIDE + k];
            float r = Rs[(ty + 16 * m) * AS_STRIDE + k];
            acc[m][0] = fmaf(a, w1.x, fmaf(r, w2.x, acc[m][0]));
            acc[m][1] = fmaf(a, w1.y, fmaf(r, w2.y, acc[m][1]));
            acc[m][2] = fmaf(a, w1.z, fmaf(r, w2.z, acc[m][2]));
            acc[m][3] = fmaf(a, w1.w, fmaf(r, w2.w, acc[m][3]));
        }
    }

    // leaky relu + partial row norms
    #pragma unroll
    for (int m = 0; m < 8; m++) {
        float local = 0.0f;
        #pragma unroll
        for (int c = 0; c < 4; c++) {
            float v = acc[m][c];
            v = (v >= 0.0f) ? v : 0.2f * v;
            acc[m][c] = v;
            local = fmaf(v, v, local);
        }
        atomicAdd(&rnorm[ty + 16 * m], local);
    }
    __syncthreads();

    int colblk = (l + 1) * 64;
    #pragma unroll
    for (int m = 0; m < 8; m++) {
        int row = ty + 16 * m;
        int n = n0 + row;
        if (n < NN) {
            float nrm = sqrtf(rnorm[row]);
            float inv = 1.0f / fmaxf(nrm, 1e-12f);
            float4 v = make_float4(acc[m][0], acc[m][1], acc[m][2], acc[m][3]);
            *(float4*)&Enext[n * DD + j0] = v;
            float4 vn = make_float4(v.x * inv, v.y * inv, v.z * inv, v.w * inv);
            *(float4*)&g_alle[n * 256 + colblk + j0] = vn;
        }
    }
}

// ---------------- final loss ----------------
__global__ void k_loss(const int* __restrict__ users,
                       const int* __restrict__ pos,
                       const int* __restrict__ neg) {
    int warp = (blockIdx.x * blockDim.x + threadIdx.x) >> 5;
    int lane = threadIdx.x & 31;
    if (warp >= NB) return;
    int uu = users[warp];
    int pp = pos[warp];
    int nn = neg[warp];
    const float4* A4 = (const float4*)g_alle;   // row = 64 float4
    float pd = 0, nd = 0, su = 0, sp = 0, sn = 0;
    #pragma unroll
    for (int t = 0; t < 2; t++) {
        float4 u = A4[uu * 64 + lane * 2 + t];
        float4 p = A4[pp * 64 + lane * 2 + t];
        float4 q = A4[nn * 64 + lane * 2 + t];
        pd += u.x * p.x + u.y * p.y + u.z * p.z + u.w * p.w;
        nd += u.x * q.x + u.y * q.y + u.z * q.z + u.w * q.w;
        su += u.x * u.x + u.y * u.y + u.z * u.z + u.w * u.w;
        sp += p.x * p.x + p.y * p.y + p.z * p.z + p.w * p.w;
        sn += q.x * q.x + q.y * q.y + q.z * q.z + q.w * q.w;
    }
    #pragma unroll
    for (int off = 16; off > 0; off >>= 1) {
        pd += __shfl_xor_sync(0xffffffffu, pd, off);
        nd += __shfl_xor_sync(0xffffffffu, nd, off);
        su += __shfl_xor_sync(0xffffffffu, su, off);
        sp += __shfl_xor_sync(0xffffffffu, sp, off);
        sn += __shfl_xor_sync(0xffffffffu, sn, off);
    }
    if (lane == 0) {
        float d = pd - nd;
        // stable log_sigmoid
        float ls = fminf(d, 0.0f) - log1pf(expf(-fabsf(d)));
        atomicAdd(&g_acc[0], ls);
        atomicAdd(&g_acc[1], su);
        atomicAdd(&g_acc[2], sp);
        atomicAdd(&g_acc[3], sn);
    }
}

__global__ void k_finalize(float* out) {
    float bpr = -g_acc[0] / (float)NB;
    float l2norm = (g_acc[1] + g_acc[2] + sqrtf(g_acc[3])) * 0.5f;
    out[0] = bpr + L2_REG * l2norm / (float)NB;
}

// ---------------- launch ----------------
extern "C" void kernel_launch(void* const* d_in, const int* in_sizes, int n_in,
                              void* d_out, int out_size) {
    const int*   users = (const int*)d_in[0];
    const int*   pos   = (const int*)d_in[1];
    const int*   neg   = (const int*)d_in[2];
    const int*   rows  = (const int*)d_in[3];
    const int*   cols  = (const int*)d_in[4];
    const float* vals  = (const float*)d_in[5];
    const float* ue    = (const float*)d_in[6];
    const float* ie    = (const float*)d_in[7];
    const float* W1    = (const float*)d_in[8];
    const float* b1    = (const float*)d_in[9];
    const float* W2    = (const float*)d_in[10];
    const float* b2    = (const float*)d_in[11];
    float* out = (float*)d_out;

    static int smem_set = 0;
    (void)smem_set;
    cudaFuncSetAttribute(k_gemm, cudaFuncAttributeMaxDynamicSharedMemorySize,
                         GEMM_SMEM_FLOATS * sizeof(float));

    // CSR build
    k_zero<<<(NN + 255) / 256, 256>>>();
    k_count<<<(NNZ + 255) / 256, 256>>>(rows);
    k_scan1<<<SCAN_NBLK, SCAN_CHUNK>>>();
    k_scan2<<<1, 32>>>();
    k_scan3<<<(NN + 255) / 256, 256>>>();
    k_scatter<<<(NNZ + 255) / 256, 256>>>(rows, cols, vals);

    // E init
    k_init_E<<<(NN * 16 + 255) / 256, 256>>>(ue, ie);

    // layers
    int cur = 0;
    for (int l = 0; l < NLAYERS; l++) {
        k_spmm<<<(NN + 7) / 8, 256>>>(cur);
        k_gemm<<<(NN + 127) / 128, 256, GEMM_SMEM_FLOATS * sizeof(float)>>>(
            cur, l, W1, b1, W2, b2);
        cur ^= 1;
    }

    // loss
    k_loss<<<(NB * 32 + 255) / 256, 256>>>(users, pos, neg);
    k_finalize<<<1, 1>>>(out);
}

// round 3
// speedup vs baseline: 1.2119x; 1.2116x over previous
#include <cuda_runtime.h>
#include <math.h>

// Problem constants
#define NU 50000
#define NI 50000
#define NN 100000          // NU + NI
#define DD 64
#define NNZ 3200000
#define NLAYERS 3
#define NB 4096
#define L2_REG 1e-5f

// scan config
#define SCAN_CHUNK 1024
#define SCAN_NBLK ((NN + SCAN_CHUNK - 1) / SCAN_CHUNK)   // 98

// ---------------- device scratch (no allocs allowed) ----------------
__device__ float g_E0[NN * DD];
__device__ float g_E1[NN * DD];
__device__ float g_Lmul[NN * DD];
__device__ float g_alle[NN * DD * (NLAYERS + 1)];   // [N, 256]
__device__ int   g_deg[NN];
__device__ int   g_rowptr[NN + 1];
__device__ int   g_cursor[NN];
__device__ int2  g_edge[NNZ];                       // (col, val bits) packed
__device__ int   g_bsum[SCAN_NBLK];
__device__ int   g_boff[SCAN_NBLK];
__device__ float g_acc[4];   // bpr_sum, sum u^2, sum p^2, sum n^2

// ---------------- f32x2 helpers (FFMA2: PTX-only pattern) ----------------
typedef unsigned long long ull;

__device__ __forceinline__ ull fma2(ull a, ull b, ull c) {
    ull d;
    asm("fma.rn.f32x2 %0, %1, %2, %3;" : "=l"(d) : "l"(a), "l"(b), "l"(c));
    return d;
}
__device__ __forceinline__ ull pk2(float lo, float hi) {
    ull d;
    asm("mov.b64 %0, {%1, %2};" : "=l"(d) : "f"(lo), "f"(hi));
    return d;
}
__device__ __forceinline__ float2 upk(ull v) {
    float2 f;
    asm("mov.b64 {%0, %1}, %2;" : "=f"(f.x), "=f"(f.y) : "l"(v));
    return f;
}

// ---------------- small setup kernels ----------------
__global__ void k_zero(void) {
    int i = blockIdx.x * blockDim.x + threadIdx.x;
    if (i < NN) g_deg[i] = 0;
    if (i < 4) g_acc[i] = 0.0f;
}

__global__ void k_count(const int* __restrict__ rows) {
    int e = blockIdx.x * blockDim.x + threadIdx.x;
    if (e < NNZ) atomicAdd(&g_deg[rows[e]], 1);
}

// inclusive scan per 1024-chunk
__global__ void k_scan1(void) {
    __shared__ int s[SCAN_CHUNK];
    int t = threadIdx.x;
    int i = blockIdx.x * SCAN_CHUNK + t;
    int v = (i < NN) ? g_deg[i] : 0;
    s[t] = v;
    __syncthreads();
    for (int off = 1; off < SCAN_CHUNK; off <<= 1) {
        int x = 0;
        if (t >= off) x = s[t - off];
        __syncthreads();
        s[t] += x;
        __syncthreads();
    }
    if (i < NN) g_rowptr[1 + i] = s[t];
    if (t == SCAN_CHUNK - 1) g_bsum[blockIdx.x] = s[t];
}

// parallel scan of the 98 block sums (was single-thread: 9us)
__global__ void k_scan2(void) {
    __shared__ int s[128];
    int t = threadIdx.x;
    int v = (t < SCAN_NBLK) ? g_bsum[t] : 0;
    s[t] = v;
    __syncthreads();
    for (int off = 1; off < 128; off <<= 1) {
        int x = 0;
        if (t >= off) x = s[t - off];
        __syncthreads();
        s[t] += x;
        __syncthreads();
    }
    if (t < SCAN_NBLK) g_boff[t] = s[t];
    if (t == 0) g_rowptr[0] = 0;
}

__global__ void k_scan3(void) {
    int i = blockIdx.x * blockDim.x + threadIdx.x;
    if (i < NN) {
        int b = i / SCAN_CHUNK;
        if (b > 0) g_rowptr[1 + i] += g_boff[b - 1];
        g_cursor[i] = g_rowptr[i];
    }
}

__global__ void k_scatter(const int* __restrict__ rows,
                          const int* __restrict__ cols,
                          const float* __restrict__ vals) {
    int e = blockIdx.x * blockDim.x + threadIdx.x;
    if (e < NNZ) {
        int r = rows[e];
        int p = atomicAdd(&g_cursor[r], 1);
        int2 pr;
        pr.x = cols[e];
        pr.y = __float_as_int(vals[e]);
        g_edge[p] = pr;
    }
}

// build E = concat(user_embed, item_embed); also write all_e block 0
__global__ void k_init_E(const float* __restrict__ ue, const float* __restrict__ ie) {
    int i = blockIdx.x * blockDim.x + threadIdx.x;
    if (i >= NN * (DD / 4)) return;
    int n = i >> 4;          // node
    int c = i & 15;          // float4 col within row
    const float4* src;
    int srow;
    if (n < NU) { src = (const float4*)ue; srow = n; }
    else        { src = (const float4*)ie; srow = n - NU; }
    float4 v = src[srow * 16 + c];
    ((float4*)g_E0)[i] = v;
    ((float4*)g_alle)[n * 64 + c] = v;
}

// ---------------- SpMM: warp per node, CSR, no atomics ----------------
__global__ void k_spmm(int cur) {
    const float* E = cur ? g_E1 : g_E0;
    int warp = (blockIdx.x * blockDim.x + threadIdx.x) >> 5;
    int lane = threadIdx.x & 31;
    if (warp >= NN) return;
    int start = g_rowptr[warp];
    int end   = g_rowptr[warp + 1];
    const float2* E2 = (const float2*)E;
    float2 acc = make_float2(0.0f, 0.0f);
    int e0 = start;
    for (; e0 + 32 <= end; e0 += 32) {
        int2 ed = g_edge[e0 + lane];
        #pragma unroll
        for (int j = 0; j < 32; j++) {
            int   cj = __shfl_sync(0xffffffffu, ed.x, j);
            float vj = __int_as_float(__shfl_sync(0xffffffffu, ed.y, j));
            float2 ev = E2[cj * 32 + lane];
            acc.x = fmaf(vj, ev.x, acc.x);
            acc.y = fmaf(vj, ev.y, acc.y);
        }
    }
    int rem = end - e0;
    if (rem > 0) {
        int2 ed = make_int2(0, 0);
        if (lane < rem) ed = g_edge[e0 + lane];
        for (int j = 0; j < rem; j++) {
            int   cj = __shfl_sync(0xffffffffu, ed.x, j);
            float vj = __int_as_float(__shfl_sync(0xffffffffu, ed.y, j));
            float2 ev = E2[cj * 32 + lane];
            acc.x = fmaf(vj, ev.x, acc.x);
            acc.y = fmaf(vj, ev.y, acc.y);
        }
    }
    ((float2*)g_Lmul)[warp * 32 + lane] = acc;
}

// ---------------- fused GEMM (FFMA2) + leaky_relu + norm + dual store ----------------
// block: 128 rows, 256 threads. tx = tid&15 -> 4 cols j0=tx*4; ty = tid>>4 -> 8
// consecutive rows r0=ty*8. A/R staged TRANSPOSED: [k][row], stride TS=132 floats
// so each thread's 8 rows load as 2 LDS.128 per operand and m-pairs feed FFMA2.
#define TS 132
#define GEMM_SMEM_FLOATS (2 * 64 * TS + 2 * 64 * 64)

__global__ void __launch_bounds__(256, 2) k_gemm(int cur, int l,
                                                 const float* __restrict__ W1,
                                                 const float* __restrict__ b1,
                                                 const float* __restrict__ W2,
                                                 const float* __restrict__ b2) {
    extern __shared__ float smem[];
    float* AsT = smem;                 // [64][132]
    float* RsT = AsT + 64 * TS;        // [64][132]
    float* W1s = RsT + 64 * TS;        // [64][64]
    float* W2s = W1s + 64 * 64;        // [64][64]

    const float* Ecur  = cur ? g_E1 : g_E0;
    float*       Enext = cur ? g_E0 : g_E1;

    int tid  = threadIdx.x;
    int lane = tid & 31;
    int wid  = tid >> 5;
    int tx = tid & 15;
    int ty = tid >> 4;
    int j0 = tx * 4;
    int r0 = ty * 8;
    int n0 = blockIdx.x * 128;
    int lw = l * 64 * 64;
    int lb = l * 64;

    // load weights
    for (int i = tid; i < 4096; i += 256) {
        W1s[i] = W1[lw + i];
        W2s[i] = W2[lw + i];
    }

    // staging: warp per row; lane covers k = 2*lane, 2*lane+1 (coalesced float2
    // global reads; 4-way-conflicted scalar STS into the transposed tiles)
    const float2* LM2 = (const float2*)g_Lmul;
    const float2* EC2 = (const float2*)Ecur;
    for (int row = wid; row < 128; row += 8) {
        int n = n0 + row;
        float2 lm = make_float2(0.0f, 0.0f), ev = make_float2(0.0f, 0.0f);
        if (n < NN) {
            lm = LM2[n * 32 + lane];
            ev = EC2[n * 32 + lane];
        }
        int k = 2 * lane;
        AsT[k * TS + row]       = lm.x + ev.x;
        AsT[(k + 1) * TS + row] = lm.y + ev.y;
        RsT[k * TS + row]       = lm.x * ev.x;
        RsT[(k + 1) * TS + row] = lm.y * ev.y;
    }
    __syncthreads();

    // accumulators: acc[p][j] = packed (row r0+2p, row r0+2p+1) for col j0+j
    ull acc[4][4];
    #pragma unroll
    for (int j = 0; j < 4; j++) {
        float b = b1[lb + j0 + j] + b2[lb + j0 + j];
        ull bb = pk2(b, b);
        #pragma unroll
        for (int p = 0; p < 4; p++) acc[p][j] = bb;
    }

    #pragma unroll 4
    for (int k = 0; k < 64; k++) {
        const float* ak = &AsT[k * TS + r0];
        const float* rk = &RsT[k * TS + r0];
        ulonglong2 A01 = *(const ulonglong2*)(ak);
        ulonglong2 A23 = *(const ulonglong2*)(ak + 4);
        ulonglong2 R01 = *(const ulonglong2*)(rk);
        ulonglong2 R23 = *(const ulonglong2*)(rk + 4);
        float4 w1 = *(const float4*)&W1s[k * 64 + j0];
        float4 w2 = *(const float4*)&W2s[k * 64 + j0];
        ull w1d[4] = { pk2(w1.x, w1.x), pk2(w1.y, w1.y), pk2(w1.z, w1.z), pk2(w1.w, w1.w) };
        ull w2d[4] = { pk2(w2.x, w2.x), pk2(w2.y, w2.y), pk2(w2.z, w2.z), pk2(w2.w, w2.w) };
        #pragma unroll
        for (int j = 0; j < 4; j++) {
            acc[0][j] = fma2(A01.x, w1d[j], acc[0][j]);
            acc[0][j] = fma2(R01.x, w2d[j], acc[0][j]);
            acc[1][j] = fma2(A01.y, w1d[j], acc[1][j]);
            acc[1][j] = fma2(R01.y, w2d[j], acc[1][j]);
            acc[2][j] = fma2(A23.x, w1d[j], acc[2][j]);
            acc[2][j] = fma2(R23.x, w2d[j], acc[2][j]);
            acc[3][j] = fma2(A23.y, w1d[j], acc[3][j]);
            acc[3][j] = fma2(R23.y, w2d[j], acc[3][j]);
        }
    }

    // leaky relu + per-row squared sums
    float vals_[8][4];
    float sq[8];
    #pragma unroll
    for (int p = 0; p < 4; p++) {
        float sx = 0.0f, sy = 0.0f;
        #pragma unroll
        for (int j = 0; j < 4; j++) {
            float2 v = upk(acc[p][j]);
            v.x = (v.x >= 0.0f) ? v.x : 0.2f * v.x;
            v.y = (v.y >= 0.0f) ? v.y : 0.2f * v.y;
            vals_[2 * p][j]     = v.x;
            vals_[2 * p + 1][j] = v.y;
            sx = fmaf(v.x, v.x, sx);
            sy = fmaf(v.y, v.y, sy);
        }
        sq[2 * p]     = sx;
        sq[2 * p + 1] = sy;
    }
    // reduce row norms across the 16 tx-lanes sharing this ty (xor <= 8 stays in group)
    #pragma unroll
    for (int i = 0; i < 8; i++) {
        #pragma unroll
        for (int off = 1; off <= 8; off <<= 1)
            sq[i] += __shfl_xor_sync(0xffffffffu, sq[i], off);
    }

    int colblk = (l + 1) * 64;
    #pragma unroll
    for (int i = 0; i < 8; i++) {
        int n = n0 + r0 + i;
        if (n < NN) {
            float inv = 1.0f / fmaxf(sqrtf(sq[i]), 1e-12f);
            float4 v = make_float4(vals_[i][0], vals_[i][1], vals_[i][2], vals_[i][3]);
            *(float4*)&Enext[n * DD + j0] = v;
            float4 vn = make_float4(v.x * inv, v.y * inv, v.z * inv, v.w * inv);
            *(float4*)&g_alle[n * 256 + colblk + j0] = vn;
        }
    }
}

// ---------------- final loss ----------------
__global__ void k_loss(const int* __restrict__ users,
                       const int* __restrict__ pos,
                       const int* __restrict__ neg) {
    int warp = (blockIdx.x * blockDim.x + threadIdx.x) >> 5;
    int lane = threadIdx.x & 31;
    if (warp >= NB) return;
    int uu = users[warp];
    int pp = pos[warp];
    int nn = neg[warp];
    const float4* A4 = (const float4*)g_alle;   // row = 64 float4
    float pd = 0, nd = 0, su = 0, sp = 0, sn = 0;
    #pragma unroll
    for (int t = 0; t < 2; t++) {
        float4 u = A4[uu * 64 + lane * 2 + t];
        float4 p = A4[pp * 64 + lane * 2 + t];
        float4 q = A4[nn * 64 + lane * 2 + t];
        pd += u.x * p.x + u.y * p.y + u.z * p.z + u.w * p.w;
        nd += u.x * q.x + u.y * q.y + u.z * q.z + u.w * q.w;
        su += u.x * u.x + u.y * u.y + u.z * u.z + u.w * u.w;
        sp += p.x * p.x + p.y * p.y + p.z * p.z + p.w * p.w;
        sn += q.x * q.x + q.y * q.y + q.z * q.z + q.w * q.w;
    }
    #pragma unroll
    for (int off = 16; off > 0; off >>= 1) {
        pd += __shfl_xor_sync(0xffffffffu, pd, off);
        nd += __shfl_xor_sync(0xffffffffu, nd, off);
        su += __shfl_xor_sync(0xffffffffu, su, off);
        sp += __shfl_xor_sync(0xffffffffu, sp, off);
        sn += __shfl_xor_sync(0xffffffffu, sn, off);
    }
    if (lane == 0) {
        float d = pd - nd;
        float ls = fminf(d, 0.0f) - log1pf(expf(-fabsf(d)));
        atomicAdd(&g_acc[0], ls);
        atomicAdd(&g_acc[1], su);
        atomicAdd(&g_acc[2], sp);
        atomicAdd(&g_acc[3], sn);
    }
}

__global__ void k_finalize(float* out) {
    float bpr = -g_acc[0] / (float)NB;
    float l2norm = (g_acc[1] + g_acc[2] + sqrtf(g_acc[3])) * 0.5f;
    out[0] = bpr + L2_REG * l2norm / (float)NB;
}

// ---------------- launch ----------------
extern "C" void kernel_launch(void* const* d_in, const int* in_sizes, int n_in,
                              void* d_out, int out_size) {
    const int*   users = (const int*)d_in[0];
    const int*   pos   = (const int*)d_in[1];
    const int*   neg   = (const int*)d_in[2];
    const int*   rows  = (const int*)d_in[3];
    const int*   cols  = (const int*)d_in[4];
    const float* vals  = (const float*)d_in[5];
    const float* ue    = (const float*)d_in[6];
    const float* ie    = (const float*)d_in[7];
    const float* W1    = (const float*)d_in[8];
    const float* b1    = (const float*)d_in[9];
    const float* W2    = (const float*)d_in[10];
    const float* b2    = (const float*)d_in[11];
    float* out = (float*)d_out;

    cudaFuncSetAttribute(k_gemm, cudaFuncAttributeMaxDynamicSharedMemorySize,
                         GEMM_SMEM_FLOATS * sizeof(float));

    // CSR build
    k_zero<<<(NN + 255) / 256, 256>>>();
    k_count<<<(NNZ + 255) / 256, 256>>>(rows);
    k_scan1<<<SCAN_NBLK, SCAN_CHUNK>>>();
    k_scan2<<<1, 128>>>();
    k_scan3<<<(NN + 255) / 256, 256>>>();
    k_scatter<<<(NNZ + 255) / 256, 256>>>(rows, cols, vals);

    // E init
    k_init_E<<<(NN * 16 + 255) / 256, 256>>>(ue, ie);

    // layers
    int cur = 0;
    for (int l = 0; l < NLAYERS; l++) {
        k_spmm<<<(NN + 7) / 8, 256>>>(cur);
        k_gemm<<<(NN + 127) / 128, 256, GEMM_SMEM_FLOATS * sizeof(float)>>>(
            cur, l, W1, b1, W2, b2);
        cur ^= 1;
    }

    // loss
    k_loss<<<(NB * 32 + 255) / 256, 256>>>(users, pos, neg);
    k_finalize<<<1, 1>>>(out);
}

// round 4
// speedup vs baseline: 1.2236x; 1.0096x over previous
#include <cuda_runtime.h>
#include <cuda_bf16.h>
#include <math.h>

// Problem constants
#define NU 50000
#define NI 50000
#define NN 100000          // NU + NI
#define DD 64
#define NNZ 3200000
#define NLAYERS 3
#define NB 4096
#define L2_REG 1e-5f

// scan config
#define SCAN_CHUNK 1024
#define SCAN_NBLK ((NN + SCAN_CHUNK - 1) / SCAN_CHUNK)   // 98

// ---------------- device scratch (no allocs allowed) ----------------
__device__ float g_E0[NN * DD];
__device__ float g_E1[NN * DD];
__device__ unsigned int g_B0[NN * DD / 2];   // bf16x2 shadow of E0
__device__ unsigned int g_B1[NN * DD / 2];   // bf16x2 shadow of E1
__device__ float g_Lmul[NN * DD];
__device__ float g_alle[NN * DD * (NLAYERS + 1)];   // [N, 256]
__device__ int   g_deg[NN];
__device__ int   g_rowptr[NN + 1];
__device__ int   g_cursor[NN];
__device__ int2  g_edge[NNZ];                       // (col, val bits) packed
__device__ int   g_bsum[SCAN_NBLK];
__device__ int   g_boff[SCAN_NBLK];
__device__ float g_acc[4];   // bpr_sum, sum u^2, sum p^2, sum n^2

// ---------------- f32x2 helpers (FFMA2: PTX-only pattern) ----------------
typedef unsigned long long ull;

__device__ __forceinline__ ull fma2(ull a, ull b, ull c) {
    ull d;
    asm("fma.rn.f32x2 %0, %1, %2, %3;" : "=l"(d) : "l"(a), "l"(b), "l"(c));
    return d;
}
__device__ __forceinline__ ull pk2(float lo, float hi) {
    ull d;
    asm("mov.b64 %0, {%1, %2};" : "=l"(d) : "f"(lo), "f"(hi));
    return d;
}
__device__ __forceinline__ float2 upk(ull v) {
    float2 f;
    asm("mov.b64 {%0, %1}, %2;" : "=f"(f.x), "=f"(f.y) : "l"(v));
    return f;
}
// pack two fp32 into bf16x2 bits (round-to-nearest)
__device__ __forceinline__ unsigned int bf2pack(float lo, float hi) {
    unsigned int r;
    asm("cvt.rn.bf16x2.f32 %0, %1, %2;" : "=r"(r) : "f"(hi), "f"(lo));
    return r;
}

// ---------------- small setup kernels ----------------
__global__ void k_zero(void) {
    int i = blockIdx.x * blockDim.x + threadIdx.x;
    if (i < NN) g_deg[i] = 0;
    if (i < 4) g_acc[i] = 0.0f;
}

__global__ void k_count(const int* __restrict__ rows) {
    int e = blockIdx.x * blockDim.x + threadIdx.x;
    if (e < NNZ) atomicAdd(&g_deg[rows[e]], 1);
}

// inclusive scan per 1024-chunk
__global__ void k_scan1(void) {
    __shared__ int s[SCAN_CHUNK];
    int t = threadIdx.x;
    int i = blockIdx.x * SCAN_CHUNK + t;
    int v = (i < NN) ? g_deg[i] : 0;
    s[t] = v;
    __syncthreads();
    for (int off = 1; off < SCAN_CHUNK; off <<= 1) {
        int x = 0;
        if (t >= off) x = s[t - off];
        __syncthreads();
        s[t] += x;
        __syncthreads();
    }
    if (i < NN) g_rowptr[1 + i] = s[t];
    if (t == SCAN_CHUNK - 1) g_bsum[blockIdx.x] = s[t];
}

__global__ void k_scan2(void) {
    __shared__ int s[128];
    int t = threadIdx.x;
    int v = (t < SCAN_NBLK) ? g_bsum[t] : 0;
    s[t] = v;
    __syncthreads();
    for (int off = 1; off < 128; off <<= 1) {
        int x = 0;
        if (t >= off) x = s[t - off];
        __syncthreads();
        s[t] += x;
        __syncthreads();
    }
    if (t < SCAN_NBLK) g_boff[t] = s[t];
    if (t == 0) g_rowptr[0] = 0;
}

__global__ void k_scan3(void) {
    int i = blockIdx.x * blockDim.x + threadIdx.x;
    if (i < NN) {
        int b = i / SCAN_CHUNK;
        if (b > 0) g_rowptr[1 + i] += g_boff[b - 1];
        g_cursor[i] = g_rowptr[i];
    }
}

__global__ void k_scatter(const int* __restrict__ rows,
                          const int* __restrict__ cols,
                          const float* __restrict__ vals) {
    int e = blockIdx.x * blockDim.x + threadIdx.x;
    if (e < NNZ) {
        int r = rows[e];
        int p = atomicAdd(&g_cursor[r], 1);
        int2 pr;
        pr.x = cols[e];
        pr.y = __float_as_int(vals[e]);
        g_edge[p] = pr;
    }
}

// build E = concat(user_embed, item_embed); also bf16 shadow + all_e block 0
__global__ void k_init_E(const float* __restrict__ ue, const float* __restrict__ ie) {
    int i = blockIdx.x * blockDim.x + threadIdx.x;
    if (i >= NN * (DD / 4)) return;
    int n = i >> 4;          // node
    int c = i & 15;          // float4 col within row
    const float4* src;
    int srow;
    if (n < NU) { src = (const float4*)ue; srow = n; }
    else        { src = (const float4*)ie; srow = n - NU; }
    float4 v = src[srow * 16 + c];
    ((float4*)g_E0)[i] = v;
    ((float4*)g_alle)[n * 64 + c] = v;
    uint2 b;
    b.x = bf2pack(v.x, v.y);
    b.y = bf2pack(v.z, v.w);
    ((uint2*)g_B0)[i] = b;
}

// ---------------- SpMM: warp per node, CSR, bf16 gather, no atomics ----------------
__global__ void __launch_bounds__(256) k_spmm(int cur) {
    const unsigned int* __restrict__ B = cur ? g_B1 : g_B0;
    __shared__ int2 sedge[8][32];
    int warp = (blockIdx.x * blockDim.x + threadIdx.x) >> 5;
    int wid  = (threadIdx.x >> 5);
    int lane = threadIdx.x & 31;
    if (warp >= NN) return;
    int start = g_rowptr[warp];
    int end   = g_rowptr[warp + 1];
    float2 acc = make_float2(0.0f, 0.0f);
    int e0 = start;
    for (; e0 + 32 <= end; e0 += 32) {
        sedge[wid][lane] = g_edge[e0 + lane];
        __syncwarp();
        #pragma unroll
        for (int j = 0; j < 32; j++) {
            int2 ed = sedge[wid][j];              // broadcast LDS.64
            float vj = __int_as_float(ed.y);
            unsigned int bits = B[ed.x * 32 + lane];
            float lo = __uint_as_float(bits << 16);
            float hi = __uint_as_float(bits & 0xffff0000u);
            acc.x = fmaf(vj, lo, acc.x);
            acc.y = fmaf(vj, hi, acc.y);
        }
        __syncwarp();
    }
    int rem = end - e0;
    if (rem > 0) {
        if (lane < rem) sedge[wid][lane] = g_edge[e0 + lane];
        __syncwarp();
        for (int j = 0; j < rem; j++) {
            int2 ed = sedge[wid][j];
            float vj = __int_as_float(ed.y);
            unsigned int bits = B[ed.x * 32 + lane];
            float lo = __uint_as_float(bits << 16);
            float hi = __uint_as_float(bits & 0xffff0000u);
            acc.x = fmaf(vj, lo, acc.x);
            acc.y = fmaf(vj, hi, acc.y);
        }
    }
    ((float2*)g_Lmul)[warp * 32 + lane] = acc;
}

// ---------------- fused GEMM (FFMA2) + leaky_relu + norm + dual store ----------------
#define TS 132
#define GEMM_SMEM_FLOATS (2 * 64 * TS + 2 * 64 * 64)

__global__ void __launch_bounds__(256, 2) k_gemm(int cur, int l,
                                                 const float* __restrict__ W1,
                                                 const float* __restrict__ b1,
                                                 const float* __restrict__ W2,
                                                 const float* __restrict__ b2) {
    extern __shared__ float smem[];
    float* AsT = smem;                 // [64][132]
    float* RsT = AsT + 64 * TS;        // [64][132]
    float* W1s = RsT + 64 * TS;        // [64][64]
    float* W2s = W1s + 64 * 64;        // [64][64]

    const float* Ecur   = cur ? g_E1 : g_E0;
    float*       Enext  = cur ? g_E0 : g_E1;
    unsigned int* Bnext = cur ? g_B0 : g_B1;

    int tid  = threadIdx.x;
    int lane = tid & 31;
    int wid  = tid >> 5;
    int tx = tid & 15;
    int ty = tid >> 4;
    int j0 = tx * 4;
    int r0 = ty * 8;
    int n0 = blockIdx.x * 128;
    int lw = l * 64 * 64;
    int lb = l * 64;

    for (int i = tid; i < 4096; i += 256) {
        W1s[i] = W1[lw + i];
        W2s[i] = W2[lw + i];
    }

    const float2* LM2 = (const float2*)g_Lmul;
    const float2* EC2 = (const float2*)Ecur;
    for (int row = wid; row < 128; row += 8) {
        int n = n0 + row;
        float2 lm = make_float2(0.0f, 0.0f), ev = make_float2(0.0f, 0.0f);
        if (n < NN) {
            lm = LM2[n * 32 + lane];
            ev = EC2[n * 32 + lane];
        }
        int k = 2 * lane;
        AsT[k * TS + row]       = lm.x + ev.x;
        AsT[(k + 1) * TS + row] = lm.y + ev.y;
        RsT[k * TS + row]       = lm.x * ev.x;
        RsT[(k + 1) * TS + row] = lm.y * ev.y;
    }
    __syncthreads();

    ull acc[4][4];
    #pragma unroll
    for (int j = 0; j < 4; j++) {
        float b = b1[lb + j0 + j] + b2[lb + j0 + j];
        ull bb = pk2(b, b);
        #pragma unroll
        for (int p = 0; p < 4; p++) acc[p][j] = bb;
    }

    #pragma unroll 4
    for (int k = 0; k < 64; k++) {
        const float* ak = &AsT[k * TS + r0];
        const float* rk = &RsT[k * TS + r0];
        ulonglong2 A01 = *(const ulonglong2*)(ak);
        ulonglong2 A23 = *(const ulonglong2*)(ak + 4);
        ulonglong2 R01 = *(const ulonglong2*)(rk);
        ulonglong2 R23 = *(const ulonglong2*)(rk + 4);
        float4 w1 = *(const float4*)&W1s[k * 64 + j0];
        float4 w2 = *(const float4*)&W2s[k * 64 + j0];
        ull w1d[4] = { pk2(w1.x, w1.x), pk2(w1.y, w1.y), pk2(w1.z, w1.z), pk2(w1.w, w1.w) };
        ull w2d[4] = { pk2(w2.x, w2.x), pk2(w2.y, w2.y), pk2(w2.z, w2.z), pk2(w2.w, w2.w) };
        #pragma unroll
        for (int j = 0; j < 4; j++) {
            acc[0][j] = fma2(A01.x, w1d[j], acc[0][j]);
            acc[0][j] = fma2(R01.x, w2d[j], acc[0][j]);
            acc[1][j] = fma2(A01.y, w1d[j], acc[1][j]);
            acc[1][j] = fma2(R01.y, w2d[j], acc[1][j]);
            acc[2][j] = fma2(A23.x, w1d[j], acc[2][j]);
            acc[2][j] = fma2(R23.x, w2d[j], acc[2][j]);
            acc[3][j] = fma2(A23.y, w1d[j], acc[3][j]);
            acc[3][j] = fma2(R23.y, w2d[j], acc[3][j]);
        }
    }

    float vals_[8][4];
    float sq[8];
    #pragma unroll
    for (int p = 0; p < 4; p++) {
        float sx = 0.0f, sy = 0.0f;
        #pragma unroll
        for (int j = 0; j < 4; j++) {
            float2 v = upk(acc[p][j]);
            v.x = (v.x >= 0.0f) ? v.x : 0.2f * v.x;
            v.y = (v.y >= 0.0f) ? v.y : 0.2f * v.y;
            vals_[2 * p][j]     = v.x;
            vals_[2 * p + 1][j] = v.y;
            sx = fmaf(v.x, v.x, sx);
            sy = fmaf(v.y, v.y, sy);
        }
        sq[2 * p]     = sx;
        sq[2 * p + 1] = sy;
    }
    #pragma unroll
    for (int i = 0; i < 8; i++) {
        #pragma unroll
        for (int off = 1; off <= 8; off <<= 1)
            sq[i] += __shfl_xor_sync(0xffffffffu, sq[i], off);
    }

    int colblk = (l + 1) * 64;
    #pragma unroll
    for (int i = 0; i < 8; i++) {
        int n = n0 + r0 + i;
        if (n < NN) {
            float inv = 1.0f / fmaxf(sqrtf(sq[i]), 1e-12f);
            float4 v = make_float4(vals_[i][0], vals_[i][1], vals_[i][2], vals_[i][3]);
            *(float4*)&Enext[n * DD + j0] = v;
            uint2 bv;
            bv.x = bf2pack(v.x, v.y);
            bv.y = bf2pack(v.z, v.w);
            *(uint2*)&Bnext[n * 32 + j0 / 2] = bv;
            float4 vn = make_float4(v.x * inv, v.y * inv, v.z * inv, v.w * inv);
            *(float4*)&g_alle[n * 256 + colblk + j0] = vn;
        }
    }
}

// ---------------- final loss ----------------
__global__ void k_loss(const int* __restrict__ users,
                       const int* __restrict__ pos,
                       const int* __restrict__ neg) {
    int warp = (blockIdx.x * blockDim.x + threadIdx.x) >> 5;
    int lane = threadIdx.x & 31;
    if (warp >= NB) return;
    int uu = users[warp];
    int pp = pos[warp];
    int nn = neg[warp];
    const float4* A4 = (const float4*)g_alle;
    float pd = 0, nd = 0, su = 0, sp = 0, sn = 0;
    #pragma unroll
    for (int t = 0; t < 2; t++) {
        float4 u = A4[uu * 64 + lane * 2 + t];
        float4 p = A4[pp * 64 + lane * 2 + t];
        float4 q = A4[nn * 64 + lane * 2 + t];
        pd += u.x * p.x + u.y * p.y + u.z * p.z + u.w * p.w;
        nd += u.x * q.x + u.y * q.y + u.z * q.z + u.w * q.w;
        su += u.x * u.x + u.y * u.y + u.z * u.z + u.w * u.w;
        sp += p.x * p.x + p.y * p.y + p.z * p.z + p.w * p.w;
        sn += q.x * q.x + q.y * q.y + q.z * q.z + q.w * q.w;
    }
    #pragma unroll
    for (int off = 16; off > 0; off >>= 1) {
        pd += __shfl_xor_sync(0xffffffffu, pd, off);
        nd += __shfl_xor_sync(0xffffffffu, nd, off);
        su += __shfl_xor_sync(0xffffffffu, su, off);
        sp += __shfl_xor_sync(0xffffffffu, sp, off);
        sn += __shfl_xor_sync(0xffffffffu, sn, off);
    }
    if (lane == 0) {
        float d = pd - nd;
        float ls = fminf(d, 0.0f) - log1pf(expf(-fabsf(d)));
        atomicAdd(&g_acc[0], ls);
        atomicAdd(&g_acc[1], su);
        atomicAdd(&g_acc[2], sp);
        atomicAdd(&g_acc[3], sn);
    }
}

__global__ void k_finalize(float* out) {
    float bpr = -g_acc[0] / (float)NB;
    float l2norm = (g_acc[1] + g_acc[2] + sqrtf(g_acc[3])) * 0.5f;
    out[0] = bpr + L2_REG * l2norm / (float)NB;
}

// ---------------- launch ----------------
extern "C" void kernel_launch(void* const* d_in, const int* in_sizes, int n_in,
                              void* d_out, int out_size) {
    const int*   users = (const int*)d_in[0];
    const int*   pos   = (const int*)d_in[1];
    const int*   neg   = (const int*)d_in[2];
    const int*   rows  = (const int*)d_in[3];
    const int*   cols  = (const int*)d_in[4];
    const float* vals  = (const float*)d_in[5];
    const float* ue    = (const float*)d_in[6];
    const float* ie    = (const float*)d_in[7];
    const float* W1    = (const float*)d_in[8];
    const float* b1    = (const float*)d_in[9];
    const float* W2    = (const float*)d_in[10];
    const float* b2    = (const float*)d_in[11];
    float* out = (float*)d_out;

    cudaFuncSetAttribute(k_gemm, cudaFuncAttributeMaxDynamicSharedMemorySize,
                         GEMM_SMEM_FLOATS * sizeof(float));

    // CSR build
    k_zero<<<(NN + 255) / 256, 256>>>();
    k_count<<<(NNZ + 255) / 256, 256>>>(rows);
    k_scan1<<<SCAN_NBLK, SCAN_CHUNK>>>();
    k_scan2<<<1, 128>>>();
    k_scan3<<<(NN + 255) / 256, 256>>>();
    k_scatter<<<(NNZ + 255) / 256, 256>>>(rows, cols, vals);

    // E init
    k_init_E<<<(NN * 16 + 255) / 256, 256>>>(ue, ie);

    // layers
    int cur = 0;
    for (int l = 0; l < NLAYERS; l++) {
        k_spmm<<<(NN + 7) / 8, 256>>>(cur);
        k_gemm<<<(NN + 127) / 128, 256, GEMM_SMEM_FLOATS * sizeof(float)>>>(
            cur, l, W1, b1, W2, b2);
        cur ^= 1;
    }

    // loss
    k_loss<<<(NB * 32 + 255) / 256, 256>>>(users, pos, neg);
    k_finalize<<<1, 1>>>(out);
}